// round 15
// baseline (speedup 1.0000x reference)
#include <cuda_runtime.h>
#include <cstdint>

// Embedding gather: out[token, :] = weight[idx[token], :]
// idx: [8192] int32, weight: [32000, 512] f32, out: [8192, 512] f32
//
// FINAL KERNEL — at the hardware floor (timed: 8.64-8.96 us, median 8.70).
//
// The read stream (~14.7 MB of unique weight rows, compulsory-miss every
// replay: no cross-launch L2 persistence, verified twice) is pinned at
// the shared L2/DRAM-side miss-tracking recycle cap:
//   45 MSHR/LTS x 128 B x 184 LTS / ~1040 cyc DRAM latency ~= 1.83 TB/s
// Measured 1.85 +/- 0.05 TB/s across EIGHT mechanisms (scalar LDG,
// smem-staged MLP=8, register MLP=4, TMA bulk copy, L2 cache policies,
// address-sorted banding, L2 prefetch pre-pass, concurrent LDG+TMA
// hybrid) and occupancy 9%-71%. Duplicate rows already L2-hit within a
// launch (DRAM traffic == unique rows). Floor = 14.7 MB / 1.83 TB/s
// ~= 8.0 us kernel ~= 8.7 us timed. Writes are L2-absorbed.
//
// Shape: 128-thr CTAs, 4 tokens/CTA, grid=2048 (single wave, 16 CTA/SM).
// No smem / no barriers. Front-batched independent gathers (MLP=4),
// fully coalesced LDG.128/STG.128; idx loads are warp-broadcast.

static constexpr int VEC_PER_ROW    = 128;  // 512 f32 = 128 float4
static constexpr int TOKENS_PER_CTA = 4;
static constexpr int THREADS        = 128;

__global__ void __launch_bounds__(THREADS, 16)
embedding_gather_kernel(const int* __restrict__ idx,
                        const float4* __restrict__ weight,
                        float4* __restrict__ out)
{
    const int tid        = threadIdx.x;            // 0..127 = vec within row
    const int base_token = blockIdx.x * TOKENS_PER_CTA;

    // Independent index loads (warp-broadcast, cached).
    int rows[TOKENS_PER_CTA];
#pragma unroll
    for (int k = 0; k < TOKENS_PER_CTA; k++)
        rows[k] = __ldg(&idx[base_token + k]);

    // Front-batched independent gathers: MLP = 4 per thread.
    float4 v[TOKENS_PER_CTA];
#pragma unroll
    for (int k = 0; k < TOKENS_PER_CTA; k++)
        v[k] = __ldg(&weight[(long long)rows[k] * VEC_PER_ROW + tid]);

#pragma unroll
    for (int k = 0; k < TOKENS_PER_CTA; k++)
        out[(long long)(base_token + k) * VEC_PER_ROW + tid] = v[k];
}

extern "C" void kernel_launch(void* const* d_in, const int* in_sizes, int n_in,
                              void* d_out, int out_size)
{
    const int*   idx    = (const int*)d_in[0];    // x: [4, 2048] int32
    const float* weight = (const float*)d_in[1];  // [32000, 512] f32
    float*       out    = (float*)d_out;          // [4, 2048, 512] f32

    const int n_tokens = in_sizes[0];             // 8192
    const int n_ctas   = n_tokens / TOKENS_PER_CTA; // 2048

    embedding_gather_kernel<<<n_ctas, THREADS>>>(
        idx, (const float4*)weight, (float4*)out);
}

// round 16
// speedup vs baseline: 1.0690x; 1.0690x over previous
#include <cuda_runtime.h>
#include <cstdint>

// Embedding gather: out[token, :] = weight[idx[token], :]
// idx: [8192] int32, weight: [32000, 512] f32, out: [8192, 512] f32
//
// FINAL KERNEL — at the hardware floor.
// Timed over 6 runs: 8.64 / 8.672 / 8.704 / 8.704 / 8.928 / 8.96 us
// (median 8.704; timer quantum 0.256 us). Kernel time 7.68-8.29 us.
//
// Why this is the floor:
// - ~14.7 MB of unique weight rows are compulsory L2 misses on every
//   graph replay. No cross-launch L2 persistence in this harness,
//   falsified twice (evict_last residency hints: neutral; full 16 MB
//   cp.async.bulk.prefetch.L2 pre-pass: gather stayed cold).
// - Cold-miss read bandwidth is pinned at 1.85 +/- 0.05 TB/s by the
//   shared L2/DRAM-side miss-tracking recycle cap:
//     45 MSHR/LTS x 128 B x 184 LTS / ~1040 cyc DRAM lat ~= 1.83 TB/s.
//   Invariant across EIGHT mechanisms: scalar LDG, smem-staged MLP=8,
//   register MLP=4, TMA bulk copy, L2 cache policies, address-sorted
//   banding (regressed), L2 prefetch pre-pass (regressed), and a
//   concurrent LDG+TMA hybrid (neutral -> cap is path-shared);
//   occupancy 9%-71%, grid 128-8192.
// - Duplicate rows already L2-hit within a launch (DRAM traffic equals
//   unique rows); output writes are L2-absorbed and do not bind.
// Floor = 14.7 MB / 1.83 TB/s ~= 8.0 us kernel ~= 8.7 us timed.
//
// Shape: 128-thr CTAs, 4 tokens/CTA, grid=2048 (single wave, 16 CTA/SM).
// No smem / no barriers. Front-batched independent gathers (MLP=4),
// fully coalesced LDG.128/STG.128; idx loads are warp-broadcast.

static constexpr int VEC_PER_ROW    = 128;  // 512 f32 = 128 float4
static constexpr int TOKENS_PER_CTA = 4;
static constexpr int THREADS        = 128;

__global__ void __launch_bounds__(THREADS, 16)
embedding_gather_kernel(const int* __restrict__ idx,
                        const float4* __restrict__ weight,
                        float4* __restrict__ out)
{
    const int tid        = threadIdx.x;            // 0..127 = vec within row
    const int base_token = blockIdx.x * TOKENS_PER_CTA;

    // Independent index loads (warp-broadcast, cached).
    int rows[TOKENS_PER_CTA];
#pragma unroll
    for (int k = 0; k < TOKENS_PER_CTA; k++)
        rows[k] = __ldg(&idx[base_token + k]);

    // Front-batched independent gathers: MLP = 4 per thread.
    float4 v[TOKENS_PER_CTA];
#pragma unroll
    for (int k = 0; k < TOKENS_PER_CTA; k++)
        v[k] = __ldg(&weight[(long long)rows[k] * VEC_PER_ROW + tid]);

#pragma unroll
    for (int k = 0; k < TOKENS_PER_CTA; k++)
        out[(long long)(base_token + k) * VEC_PER_ROW + tid] = v[k];
}

extern "C" void kernel_launch(void* const* d_in, const int* in_sizes, int n_in,
                              void* d_out, int out_size)
{
    const int*   idx    = (const int*)d_in[0];    // x: [4, 2048] int32
    const float* weight = (const float*)d_in[1];  // [32000, 512] f32
    float*       out    = (float*)d_out;          // [4, 2048, 512] f32

    const int n_tokens = in_sizes[0];             // 8192
    const int n_ctas   = n_tokens / TOKENS_PER_CTA; // 2048

    embedding_gather_kernel<<<n_ctas, THREADS>>>(
        idx, (const float4*)weight, (float4*)out);
}